// round 11
// baseline (speedup 1.0000x reference)
#include <cuda_runtime.h>
#include <math.h>
#include <stdint.h>

// Problem constants
#define B_   64
#define IN_  512
#define M_   1024
#define NG   6          // q,k,v,i,f,o
#define NSPLIT 4
#define KSL  (IN_ / NSPLIT)   // 128
#define PSTRIDE ((size_t)B_ * NG * M_)   // per-split stride in g_part

// split-K partials: [s][b][gate*M + m]
__device__ float g_part[NSPLIT * B_ * NG * M_];

__device__ __forceinline__ float sigmoidf_(float v) {
    return 1.f / (1.f + __expf(-v));
}

// reduce a float4 across the NSPLIT partial buffers
__device__ __forceinline__ float4 reduce4(const float* base) {
    float4 a = *(const float4*)base;
    #pragma unroll
    for (int s = 1; s < NSPLIT; s++) {
        float4 p = *(const float4*)(base + s * PSTRIDE);
        a.x += p.x; a.y += p.y; a.z += p.z; a.w += p.w;
    }
    return a;
}

// reduce a scalar across the NSPLIT partial buffers
__device__ __forceinline__ float reduce1(const float* base) {
    float a = *base;
    #pragma unroll
    for (int s = 1; s < NSPLIT; s++) a += base[s * PSTRIDE];
    return a;
}

// ---------------------------------------------------------------------------
// TF32 helpers
// ---------------------------------------------------------------------------
__device__ __forceinline__ uint32_t f2tf32(float f) {
    uint32_t u;
    asm("cvt.rna.tf32.f32 %0, %1;" : "=r"(u) : "f"(f));
    return u;
}

__device__ __forceinline__ void mma_tf32(float* c, const uint32_t* a, const uint32_t* b) {
    asm("mma.sync.aligned.m16n8k8.row.col.f32.tf32.tf32.f32 "
        "{%0,%1,%2,%3},{%4,%5,%6,%7},{%8,%9},{%0,%1,%2,%3};"
        : "+f"(c[0]), "+f"(c[1]), "+f"(c[2]), "+f"(c[3])
        : "r"(a[0]), "r"(a[1]), "r"(a[2]), "r"(a[3]),
          "r"(b[0]), "r"(b[1]));
}

// ---------------------------------------------------------------------------
// Kernel 1: split-K TF32 tensor-core GEMM partials (unchanged, measured 10.6us)
// grid = (96, 4). Block tile 64x64x32 double-buffered, warp grid 2m x 4n.
// ---------------------------------------------------------------------------
__global__ __launch_bounds__(256)
void gates_mma_sk(const float* __restrict__ x,
                  const float* __restrict__ Wq, const float* __restrict__ Wk,
                  const float* __restrict__ Wv, const float* __restrict__ Wi,
                  const float* __restrict__ Wf, const float* __restrict__ Wo)
{
    const int n_global0 = blockIdx.x * 64;          // [0, 6144)
    const int gate      = n_global0 >> 10;
    const int n_local0  = n_global0 & (M_ - 1);
    const int s         = blockIdx.y;
    const int k_base    = s * KSL;

    const float* W;
    switch (gate) {
        case 0: W = Wq; break;
        case 1: W = Wk; break;
        case 2: W = Wv; break;
        case 3: W = Wi; break;
        case 4: W = Wf; break;
        default: W = Wo; break;
    }

    __shared__ uint32_t Xs[2][64][36];   // [buf][b][k] tf32 bits
    __shared__ uint32_t Ws[2][64][36];   // [buf][n][k] tf32 bits

    const int tid  = threadIdx.x;
    const int wid  = tid >> 5;
    const int lane = tid & 31;
    const int g    = lane >> 2;
    const int tig  = lane & 3;
    const int warp_m = wid & 1;
    const int warp_n = wid >> 1;

    const int lrow0 = tid >> 3;
    const int lrow1 = lrow0 + 32;
    const int lcol  = (tid & 7) * 4;

    const float* xg0 = x + lrow0 * IN_ + k_base + lcol;
    const float* xg1 = x + lrow1 * IN_ + k_base + lcol;
    const float* wg0 = W + (n_local0 + lrow0) * IN_ + k_base + lcol;
    const float* wg1 = W + (n_local0 + lrow1) * IN_ + k_base + lcol;

    float acc[2][2][4];
    #pragma unroll
    for (int mt = 0; mt < 2; mt++)
        #pragma unroll
        for (int nt = 0; nt < 2; nt++)
            #pragma unroll
            for (int e = 0; e < 4; e++) acc[mt][nt][e] = 0.f;

    float4 xr0, xr1, wr0, wr1;
    xr0 = *(const float4*)xg0;
    xr1 = *(const float4*)xg1;
    wr0 = *(const float4*)wg0;
    wr1 = *(const float4*)wg1;

    {
        uint4 u;
        u.x = f2tf32(xr0.x); u.y = f2tf32(xr0.y); u.z = f2tf32(xr0.z); u.w = f2tf32(xr0.w);
        *(uint4*)&Xs[0][lrow0][lcol] = u;
        u.x = f2tf32(xr1.x); u.y = f2tf32(xr1.y); u.z = f2tf32(xr1.z); u.w = f2tf32(xr1.w);
        *(uint4*)&Xs[0][lrow1][lcol] = u;
        u.x = f2tf32(wr0.x); u.y = f2tf32(wr0.y); u.z = f2tf32(wr0.z); u.w = f2tf32(wr0.w);
        *(uint4*)&Ws[0][lrow0][lcol] = u;
        u.x = f2tf32(wr1.x); u.y = f2tf32(wr1.y); u.z = f2tf32(wr1.z); u.w = f2tf32(wr1.w);
        *(uint4*)&Ws[0][lrow1][lcol] = u;
    }
    __syncthreads();

    int buf = 0;
    #pragma unroll 1
    for (int it = 0; it < KSL / 32; it++) {
        if (it < KSL / 32 - 1) {
            const int k0 = (it + 1) * 32;
            xr0 = *(const float4*)(xg0 + k0);
            xr1 = *(const float4*)(xg1 + k0);
            wr0 = *(const float4*)(wg0 + k0);
            wr1 = *(const float4*)(wg1 + k0);
        }

        #pragma unroll
        for (int ks = 0; ks < 4; ks++) {
            const int ko = ks * 8;
            uint32_t af[2][4];
            #pragma unroll
            for (int mt = 0; mt < 2; mt++) {
                const int r = warp_m * 32 + mt * 16 + g;
                af[mt][0] = Xs[buf][r][ko + tig];
                af[mt][1] = Xs[buf][r + 8][ko + tig];
                af[mt][2] = Xs[buf][r][ko + tig + 4];
                af[mt][3] = Xs[buf][r + 8][ko + tig + 4];
            }
            uint32_t bfr[2][2];
            #pragma unroll
            for (int nt = 0; nt < 2; nt++) {
                const int c = warp_n * 16 + nt * 8 + g;
                bfr[nt][0] = Ws[buf][c][ko + tig];
                bfr[nt][1] = Ws[buf][c][ko + tig + 4];
            }
            #pragma unroll
            for (int mt = 0; mt < 2; mt++)
                #pragma unroll
                for (int nt = 0; nt < 2; nt++)
                    mma_tf32(acc[mt][nt], af[mt], bfr[nt]);
        }

        if (it < KSL / 32 - 1) {
            const int nb = buf ^ 1;
            uint4 u;
            u.x = f2tf32(xr0.x); u.y = f2tf32(xr0.y); u.z = f2tf32(xr0.z); u.w = f2tf32(xr0.w);
            *(uint4*)&Xs[nb][lrow0][lcol] = u;
            u.x = f2tf32(xr1.x); u.y = f2tf32(xr1.y); u.z = f2tf32(xr1.z); u.w = f2tf32(xr1.w);
            *(uint4*)&Xs[nb][lrow1][lcol] = u;
            u.x = f2tf32(wr0.x); u.y = f2tf32(wr0.y); u.z = f2tf32(wr0.z); u.w = f2tf32(wr0.w);
            *(uint4*)&Ws[nb][lrow0][lcol] = u;
            u.x = f2tf32(wr1.x); u.y = f2tf32(wr1.y); u.z = f2tf32(wr1.z); u.w = f2tf32(wr1.w);
            *(uint4*)&Ws[nb][lrow1][lcol] = u;
            __syncthreads();
            buf = nb;
        }
    }

    // write raw partials (L2-resident)
    float* outp = g_part + (size_t)s * PSTRIDE;
    #pragma unroll
    for (int mt = 0; mt < 2; mt++) {
        const int r0 = warp_m * 32 + mt * 16 + g;
        #pragma unroll
        for (int nt = 0; nt < 2; nt++) {
            const int ncol = n_global0 + warp_n * 16 + nt * 8 + 2 * tig;
            *(float2*)&outp[(size_t)r0 * (NG * M_) + ncol] =
                make_float2(acc[mt][nt][0], acc[mt][nt][1]);
            *(float2*)&outp[(size_t)(r0 + 8) * (NG * M_) + ncol] =
                make_float2(acc[mt][nt][2], acc[mt][nt][3]);
        }
    }
}

// ---------------------------------------------------------------------------
// Kernel 2 (fully fused): split-K reduce + bias + activation + n_t + denom +
// streaming C_t update + h_tilde + h_t.  grid = (16, 64).
// Stage 1: all threads reduce q,k,i,f over splits (L2-resident), activate,
//          build sk/sq, n_t (bx==0 writes out_n), block-reduce denom.
// Stage 2: threads<64 reduce f,i,v,o for the block's 64 rows -> fm/cm/om smem.
// Main loop: cross-row pipelined streaming C update (R7 structure).
// ---------------------------------------------------------------------------
__global__ __launch_bounds__(256)
void update_C(const float* __restrict__ Cprev, const float* __restrict__ nprev,
              const float* __restrict__ bq, const float* __restrict__ bk,
              const float* __restrict__ bv, const float* __restrict__ bi,
              const float* __restrict__ bf, const float* __restrict__ bo,
              float* __restrict__ Cout, float* __restrict__ out_h,
              float* __restrict__ out_n)
{
    const int b = blockIdx.y;
    __shared__ float sk[M_];
    __shared__ float sq[M_];
    __shared__ float s_fm[64], s_cm[64], s_om[64];
    __shared__ float red[8];
    __shared__ float s_inv;

    const float* pb = g_part + (size_t)b * (NG * M_);   // split 0, this batch
    const int t    = threadIdx.x;
    const int warp = t >> 5;
    const int lane = t & 31;

    // --- stage 1: reduce+activate q,k,i,f ; n_t ; denom partial ---
    {
        float4 q4 = reduce4(pb + 0 * M_ + 4 * t);
        float4 k4 = reduce4(pb + 1 * M_ + 4 * t);
        float4 i4 = reduce4(pb + 3 * M_ + 4 * t);
        float4 f4 = reduce4(pb + 4 * M_ + 4 * t);
        const float4 bq4 = ((const float4*)bq)[t];
        const float4 bk4 = ((const float4*)bk)[t];
        const float4 bi4 = ((const float4*)bi)[t];
        const float4 bf4 = ((const float4*)bf)[t];

        q4.x += bq4.x; q4.y += bq4.y; q4.z += bq4.z; q4.w += bq4.w;
        k4.x = (k4.x + bk4.x) * 0.03125f;
        k4.y = (k4.y + bk4.y) * 0.03125f;
        k4.z = (k4.z + bk4.z) * 0.03125f;
        k4.w = (k4.w + bk4.w) * 0.03125f;
        i4.x = __expf(i4.x + bi4.x);
        i4.y = __expf(i4.y + bi4.y);
        i4.z = __expf(i4.z + bi4.z);
        i4.w = __expf(i4.w + bi4.w);
        f4.x = sigmoidf_(f4.x + bf4.x);
        f4.y = sigmoidf_(f4.y + bf4.y);
        f4.z = sigmoidf_(f4.z + bf4.z);
        f4.w = sigmoidf_(f4.w + bf4.w);

        ((float4*)sk)[t] = k4;
        ((float4*)sq)[t] = q4;

        float4 p4 = ((const float4*)(nprev + b * M_))[t];
        float4 n4;
        n4.x = fmaf(f4.x, p4.x, i4.x * k4.x);
        n4.y = fmaf(f4.y, p4.y, i4.y * k4.y);
        n4.z = fmaf(f4.z, p4.z, i4.z * k4.z);
        n4.w = fmaf(f4.w, p4.w, i4.w * k4.w);
        if (blockIdx.x == 0)
            ((float4*)(out_n + b * M_))[t] = n4;

        float part = n4.x * q4.x + n4.y * q4.y + n4.z * q4.z + n4.w * q4.w;
        #pragma unroll
        for (int off = 16; off; off >>= 1)
            part += __shfl_xor_sync(0xffffffffu, part, off);
        if (lane == 0) red[warp] = part;
    }

    // --- stage 2: per-row gate scalars for this block's 64 rows ---
    if (t < 64) {
        const int m = blockIdx.x * 64 + t;
        float fv = reduce1(pb + 4 * M_ + m);
        float iv = reduce1(pb + 3 * M_ + m);
        float vv = reduce1(pb + 2 * M_ + m);
        float ov = reduce1(pb + 5 * M_ + m);
        float fm = sigmoidf_(fv + bf[m]);
        s_fm[t] = fm;
        s_cm[t] = __expf(iv + bi[m]) * (vv + bv[m]);
        s_om[t] = sigmoidf_(ov + bo[m]);
    }

    __syncthreads();
    if (t == 0) {
        float d = red[0] + red[1] + red[2] + red[3]
                + red[4] + red[5] + red[6] + red[7];
        s_inv = 1.0f / fmaxf(d, 1.0f);
    }
    __syncthreads();
    const float inv = s_inv;

    const float4* sk4 = (const float4*)sk;
    const float4* sq4 = (const float4*)sq;

    const int m_base = blockIdx.x * 64 + warp;

    // --- main loop: cross-row pipelined streaming C update ---
    float4 cur[8], nxt[8];
    int m = m_base;
    float fm = s_fm[warp];
    float cm = s_cm[warp];
    {
        const float4* cp = (const float4*)(Cprev + ((size_t)b * M_ + m) * M_);
        #pragma unroll
        for (int j = 0; j < 8; j++) cur[j] = __ldcs(cp + j * 32 + lane);
    }

    #pragma unroll
    for (int r = 0; r < 8; r++) {
        float fmn = 0.f, cmn = 0.f;
        if (r < 7) {
            const int mn = m_base + (r + 1) * 8;
            fmn = s_fm[(r + 1) * 8 + warp];
            cmn = s_cm[(r + 1) * 8 + warp];
            const float4* cpn = (const float4*)(Cprev + ((size_t)b * M_ + mn) * M_);
            #pragma unroll
            for (int j = 0; j < 8; j++) nxt[j] = __ldcs(cpn + j * 32 + lane);
        }

        float4* co = (float4*)(Cout + ((size_t)b * M_ + m) * M_);
        float dot0 = 0.f, dot1 = 0.f;
        #pragma unroll
        for (int j = 0; j < 8; j++) {
            const int n4 = j * 32 + lane;
            float4 kk = sk4[n4];
            float4 qq = sq4[n4];
            float4 o;
            o.x = fmaf(fm, cur[j].x, cm * kk.x);
            o.y = fmaf(fm, cur[j].y, cm * kk.y);
            o.z = fmaf(fm, cur[j].z, cm * kk.z);
            o.w = fmaf(fm, cur[j].w, cm * kk.w);
            __stcs(co + n4, o);
            if (j & 1) {
                dot1 = fmaf(o.x, qq.x, dot1);
                dot1 = fmaf(o.y, qq.y, dot1);
                dot1 = fmaf(o.z, qq.z, dot1);
                dot1 = fmaf(o.w, qq.w, dot1);
            } else {
                dot0 = fmaf(o.x, qq.x, dot0);
                dot0 = fmaf(o.y, qq.y, dot0);
                dot0 = fmaf(o.z, qq.z, dot0);
                dot0 = fmaf(o.w, qq.w, dot0);
            }
        }
        float dot = dot0 + dot1;
        #pragma unroll
        for (int off = 16; off; off >>= 1)
            dot += __shfl_xor_sync(0xffffffffu, dot, off);
        if (lane == 0)
            out_h[b * M_ + m] = s_om[r * 8 + warp] * dot * inv;

        m = m_base + (r + 1) * 8;
        fm = fmn;
        cm = cmn;
        #pragma unroll
        for (int j = 0; j < 8; j++) cur[j] = nxt[j];
    }
}

// ---------------------------------------------------------------------------
// Launch. Inputs (metadata order):
// 0 x, 1 h_prev, 2 c_prev, 3 C_prev, 4 n_prev, 5 m_prev,
// 6 Wq, 7 bq, 8 Wk, 9 bk, 10 Wv, 11 bv, 12 Wi, 13 bi, 14 Wf, 15 bf, 16 Wo, 17 bo
// Output: concat(h_t [64*1024], C_t [64*1024*1024], n_t [64*1024])
// ---------------------------------------------------------------------------
extern "C" void kernel_launch(void* const* d_in, const int* in_sizes, int n_in,
                              void* d_out, int out_size)
{
    const float* x     = (const float*)d_in[0];
    const float* Cprev = (const float*)d_in[3];
    const float* nprev = (const float*)d_in[4];

    const float* Wq = (const float*)d_in[6];  const float* bq = (const float*)d_in[7];
    const float* Wk = (const float*)d_in[8];  const float* bk = (const float*)d_in[9];
    const float* Wv = (const float*)d_in[10]; const float* bv = (const float*)d_in[11];
    const float* Wi = (const float*)d_in[12]; const float* bi = (const float*)d_in[13];
    const float* Wf = (const float*)d_in[14]; const float* bf = (const float*)d_in[15];
    const float* Wo = (const float*)d_in[16]; const float* bo = (const float*)d_in[17];

    float* out   = (float*)d_out;
    float* out_h = out;                                    // [64*1024]
    float* out_C = out + (size_t)B_ * M_;                  // [64*1024*1024]
    float* out_n = out + (size_t)B_ * M_ + (size_t)B_ * M_ * M_;

    dim3 grid1(96, NSPLIT);
    gates_mma_sk<<<grid1, 256>>>(x, Wq, Wk, Wv, Wi, Wf, Wo);

    dim3 grid2(16, 64);
    update_C<<<grid2, 256>>>(Cprev, nprev, bq, bk, bv, bi, bf, bo,
                             out_C, out_h, out_n);
}